// round 6
// baseline (speedup 1.0000x reference)
#include <cuda_runtime.h>
#include <cuda_bf16.h>

#define N_NODES 100000
#define N_EDGES 1600000
#define TOT_E   (N_EDGES + N_NODES)   // edges + self loops
#define SCAN_NB 98                     // ceil(100000/1024)

// ---------------- scratch (__device__ globals; no allocations) ----------------
__device__ int    g_cur[N_NODES];
__device__ int    g_rowptr[N_NODES + 1];
__device__ int    g_csr[TOT_E];
__device__ int    g_bsum[SCAN_NB];
__device__ float  g_h1[N_NODES * 128];
__device__ float  g_out1[N_NODES * 128];
__device__ float  g_h2[N_NODES * 128];
__device__ float  g_as1[N_NODES * 2], g_ad1[N_NODES * 2];
__device__ float  g_as2[N_NODES * 2], g_ad2[N_NODES * 2];
__device__ float  g_colsum[128], g_colsq[128];
__device__ float  g_W2p[128 * 128];
__device__ float  g_biasEff[128];
__device__ float  g_attS2p[128], g_attD2p[128];

// ---------------- streams/events for capture-time fork (created at load) ------
static cudaStream_t g_s2 = nullptr;
static cudaEvent_t  g_e1 = nullptr, g_e2 = nullptr;
namespace {
struct StreamInit {
    StreamInit() {
        if (cudaStreamCreateWithFlags(&g_s2, cudaStreamNonBlocking) != cudaSuccess) { g_s2 = nullptr; return; }
        if (cudaEventCreateWithFlags(&g_e1, cudaEventDisableTiming) != cudaSuccess ||
            cudaEventCreateWithFlags(&g_e2, cudaEventDisableTiming) != cudaSuccess) {
            g_s2 = nullptr;
        }
    }
};
StreamInit g_stream_init;
}

// ---------------- CSR build ----------------
__global__ void init_k() {
    int i = blockIdx.x * blockDim.x + threadIdx.x;
    if (i < N_NODES) g_cur[i] = 1;          // self loop
    if (i < 128) { g_colsum[i] = 0.f; g_colsq[i] = 0.f; }
}

__global__ void count_k(const int* __restrict__ ei) {
    int e = blockIdx.x * blockDim.x + threadIdx.x;
    if (e < N_EDGES) atomicAdd(&g_cur[ei[N_EDGES + e]], 1);
}

__global__ void scan1_k() {
    __shared__ int sh[1024];
    int i = blockIdx.x * 1024 + threadIdx.x;
    int v = (i < N_NODES) ? g_cur[i] : 0;
    sh[threadIdx.x] = v;
    __syncthreads();
    for (int off = 1; off < 1024; off <<= 1) {
        int t = (threadIdx.x >= off) ? sh[threadIdx.x - off] : 0;
        __syncthreads();
        sh[threadIdx.x] += t;
        __syncthreads();
    }
    if (i < N_NODES) g_rowptr[i] = sh[threadIdx.x] - v;   // local exclusive
    if (threadIdx.x == 1023) g_bsum[blockIdx.x] = sh[1023];
}

__global__ void scan2_k() {                 // parallel scan over 98 block sums
    __shared__ int sh[128];
    int t = threadIdx.x;
    int v = (t < SCAN_NB) ? g_bsum[t] : 0;
    sh[t] = v;
    __syncthreads();
    for (int off = 1; off < 128; off <<= 1) {
        int u = (t >= off) ? sh[t - off] : 0;
        __syncthreads();
        sh[t] += u;
        __syncthreads();
    }
    if (t < SCAN_NB) g_bsum[t] = sh[t] - v;   // exclusive
}

__global__ void scan3_k() {
    int i = blockIdx.x * 1024 + threadIdx.x;
    if (i < N_NODES) {
        int r = g_rowptr[i] + g_bsum[blockIdx.x];
        g_rowptr[i] = r;
        g_cur[i]    = r;
    }
    if (i == 0) g_rowptr[N_NODES] = TOT_E;
}

__global__ void fill_k(const int* __restrict__ ei) {
    int idx = blockIdx.x * blockDim.x + threadIdx.x;
    if (idx >= TOT_E) return;
    int s, d;
    if (idx < N_EDGES) { s = ei[idx]; d = ei[N_EDGES + idx]; }
    else               { s = d = idx - N_EDGES; }
    int p = atomicAdd(&g_cur[d], 1);
    g_csr[p] = s;
}

// ---------------- GEMM + bias + fused attention dots ----------------
// h = A @ W + B ; as[n,h]/ad[n,h] = per-head dot of h-row with att vectors.
// L==1: A=x, W=W1, B=b1, S/D = att_src1/att_dst1 -> g_h1, g_as1, g_ad1
// L==2: A=g_out1, W=g_W2p, B=g_biasEff, S/D = g_attS2p/g_attD2p -> g_h2, g_as2, g_ad2
template <int L>
__global__ __launch_bounds__(256) void gemm_att_k(const float* __restrict__ A_in,
                                                  const float* __restrict__ W_in,
                                                  const float* __restrict__ B_in,
                                                  const float* __restrict__ S_in,
                                                  const float* __restrict__ D_in) {
    const float* __restrict__ A = (L == 1) ? A_in : g_out1;
    const float* __restrict__ W = (L == 1) ? W_in : g_W2p;
    const float* __restrict__ B = (L == 1) ? B_in : g_biasEff;
    const float* __restrict__ S = (L == 1) ? S_in : g_attS2p;
    const float* __restrict__ D = (L == 1) ? D_in : g_attD2p;
    float* __restrict__ C  = (L == 1) ? g_h1 : g_h2;
    float* __restrict__ as = (L == 1) ? g_as1 : g_as2;
    float* __restrict__ ad = (L == 1) ? g_ad1 : g_ad2;

    __shared__ float Ws[32][128];
    __shared__ float Xs[64][32];
    int tid = threadIdx.x;
    int tx = tid & 31, ty = tid >> 5;
    int row0 = blockIdx.x * 64;

    float acc[8][4];
#pragma unroll
    for (int i = 0; i < 8; i++) { acc[i][0] = acc[i][1] = acc[i][2] = acc[i][3] = 0.f; }

    for (int kk = 0; kk < 128; kk += 32) {
#pragma unroll
        for (int l = 0; l < 4; l++) {            // Ws: 32x128 floats
            int f = (l * 256 + tid) * 4;
            int r = f >> 7, c = f & 127;
            *(float4*)&Ws[r][c] = *(const float4*)&W[(kk + r) * 128 + c];
        }
#pragma unroll
        for (int l = 0; l < 2; l++) {            // Xs: 64x32 floats
            int f = (l * 256 + tid) * 4;
            int r = f >> 5, c = f & 31;
            int gr = row0 + r;
            float4 v = make_float4(0.f, 0.f, 0.f, 0.f);
            if (gr < N_NODES) v = *(const float4*)&A[gr * 128 + kk + c];
            *(float4*)&Xs[r][c] = v;
        }
        __syncthreads();
#pragma unroll
        for (int k = 0; k < 32; k++) {
            float4 bv = *(float4*)&Ws[k][tx * 4];
#pragma unroll
            for (int i = 0; i < 8; i++) {
                float a = Xs[ty * 8 + i][k];
                acc[i][0] += a * bv.x; acc[i][1] += a * bv.y;
                acc[i][2] += a * bv.z; acc[i][3] += a * bv.w;
            }
        }
        __syncthreads();
    }
    float4 bv = *(const float4*)&B[tx * 4];
    float4 s4 = *(const float4*)&S[tx * 4];
    float4 d4 = *(const float4*)&D[tx * 4];
#pragma unroll
    for (int i = 0; i < 8; i++) {
        int r = row0 + ty * 8 + i;
        float4 o = make_float4(acc[i][0] + bv.x, acc[i][1] + bv.y,
                               acc[i][2] + bv.z, acc[i][3] + bv.w);
        if (r < N_NODES)
            *(float4*)&C[r * 128 + tx * 4] = o;
        // fused attention dots: head0 = lanes 0..15 (cols 0..63), head1 = lanes 16..31
        float ps = o.x * s4.x + o.y * s4.y + o.z * s4.z + o.w * s4.w;
        float pd = o.x * d4.x + o.y * d4.y + o.z * d4.z + o.w * d4.w;
#pragma unroll
        for (int off = 8; off; off >>= 1) {
            ps += __shfl_xor_sync(0xffffffffu, ps, off);
            pd += __shfl_xor_sync(0xffffffffu, pd, off);
        }
        if (r < N_NODES) {
            if (tx == 0)  { as[r * 2]     = ps; ad[r * 2]     = pd; }
            if (tx == 16) { as[r * 2 + 1] = ps; ad[r * 2 + 1] = pd; }
        }
    }
}

// ---------------- warp-per-node single-pass GAT aggregation ----------------
// Softmax is shift-invariant; alphas are O(1), so exp without max-subtraction is
// safe and identical. Every lane in a half-warp computes the same e per edge, so
// each lane's running sum IS the head's denominator — no reduction needed.
// L==1: out1[n][128] = agg + b1
// L==2: d_out[n][40] = log_softmax(mean_heads(agg) + b2)
template <int L>
__global__ __launch_bounds__(256) void agg_k(const float* __restrict__ bias,
                                             float* __restrict__ out_final) {
    int gw = (blockIdx.x * blockDim.x + threadIdx.x) >> 5;
    int lane = threadIdx.x & 31;
    if (gw >= N_NODES) return;
    const float* __restrict__ h  = (L == 1) ? g_h1 : g_h2;
    const float* __restrict__ as = (L == 1) ? g_as1 : g_as2;
    const float* __restrict__ ad = (L == 1) ? g_ad1 : g_ad2;

    int n = gw;
    int beg = g_rowptr[n], end = g_rowptr[n + 1];
    bool head0 = (lane < 16);
    float add = head0 ? ad[n * 2] : ad[n * 2 + 1];
    int col = lane * 4;

    float a0 = 0.f, a1 = 0.f, a2 = 0.f, a3 = 0.f, dsum = 0.f;
#pragma unroll 2
    for (int i = beg; i < end; i++) {
        int s = __ldg(&g_csr[i]);                       // broadcast
        float2 a = *(const float2*)&as[s * 2];          // broadcast
        float x = (head0 ? a.x : a.y) + add;
        x = x > 0.f ? x : 0.2f * x;                     // leaky relu
        float e = __expf(x);
        dsum += e;
        float4 hv = *(const float4*)&h[s * 128 + col];  // coalesced 512B row
        a0 += e * hv.x; a1 += e * hv.y; a2 += e * hv.z; a3 += e * hv.w;
    }
    float inv = 1.0f / dsum;
    a0 *= inv; a1 *= inv; a2 *= inv; a3 *= inv;

    if (L == 1) {
        float4 bv = *(const float4*)&bias[col];
        float4 o = make_float4(a0 + bv.x, a1 + bv.y, a2 + bv.z, a3 + bv.w);
        *(float4*)&g_out1[n * 128 + col] = o;
    } else {
        // pair heads: head1 col c lives at padded col 64+c (lane 16+c/4)
        float p0 = __shfl_down_sync(0xffffffffu, a0, 16);
        float p1 = __shfl_down_sync(0xffffffffu, a1, 16);
        float p2 = __shfl_down_sync(0xffffffffu, a2, 16);
        float p3 = __shfl_down_sync(0xffffffffu, a3, 16);
        bool valid = (lane < 10);                 // cols lane*4..+3 all < 40
        float z0 = -1e30f, z1 = -1e30f, z2 = -1e30f, z3 = -1e30f;
        if (valid) {
            float4 b2v = *(const float4*)&bias[lane * 4];
            z0 = 0.5f * (a0 + p0) + b2v.x;
            z1 = 0.5f * (a1 + p1) + b2v.y;
            z2 = 0.5f * (a2 + p2) + b2v.z;
            z3 = 0.5f * (a3 + p3) + b2v.w;
        }
        float mx = fmaxf(fmaxf(z0, z1), fmaxf(z2, z3));
#pragma unroll
        for (int off = 16; off; off >>= 1)
            mx = fmaxf(mx, __shfl_xor_sync(0xffffffffu, mx, off));
        float se = 0.f;
        if (valid)
            se = __expf(z0 - mx) + __expf(z1 - mx) + __expf(z2 - mx) + __expf(z3 - mx);
#pragma unroll
        for (int off = 16; off; off >>= 1)
            se += __shfl_xor_sync(0xffffffffu, se, off);
        float lse = __logf(se) + mx;
        if (valid) {
            float4 o = make_float4(z0 - lse, z1 - lse, z2 - lse, z3 - lse);
            *(float4*)&out_final[n * 40 + lane * 4] = o;
        }
    }
}

// ---------------- BatchNorm stats over g_out1 ----------------
__global__ void bn_stats_k() {
    int lane = threadIdx.x;   // 0..31 -> 4 columns each
    int wy = threadIdx.y;     // 0..7
    float s0 = 0, s1 = 0, s2 = 0, s3 = 0, q0 = 0, q1 = 0, q2 = 0, q3 = 0;
    for (int n = blockIdx.x * 8 + wy; n < N_NODES; n += gridDim.x * 8) {
        float4 v = *(const float4*)&g_out1[n * 128 + lane * 4];
        s0 += v.x; q0 += v.x * v.x;
        s1 += v.y; q1 += v.y * v.y;
        s2 += v.z; q2 += v.z * v.z;
        s3 += v.w; q3 += v.w * v.w;
    }
    __shared__ float sh[8][128];
    __shared__ float shq[8][128];
    sh[wy][lane * 4 + 0] = s0; shq[wy][lane * 4 + 0] = q0;
    sh[wy][lane * 4 + 1] = s1; shq[wy][lane * 4 + 1] = q1;
    sh[wy][lane * 4 + 2] = s2; shq[wy][lane * 4 + 2] = q2;
    sh[wy][lane * 4 + 3] = s3; shq[wy][lane * 4 + 3] = q3;
    __syncthreads();
    if (wy == 0) {
#pragma unroll
        for (int j = 0; j < 4; j++) {
            float ts = 0.f, tq = 0.f;
            for (int w = 0; w < 8; w++) { ts += sh[w][lane * 4 + j]; tq += shq[w][lane * 4 + j]; }
            atomicAdd(&g_colsum[lane * 4 + j], ts);
            atomicAdd(&g_colsq[lane * 4 + j], tq);
        }
    }
}

// ---------------- fold BN into W2 + build padded layer2 params ----------------
__global__ void prep_k(const float* __restrict__ gamma, const float* __restrict__ beta,
                       const float* __restrict__ W2,
                       const float* __restrict__ as2, const float* __restrict__ ad2) {
    int j = threadIdx.x;   // 128 threads
    __shared__ float s_scale[128], s_shift[128];
    float mean = g_colsum[j] * (1.0f / N_NODES);
    float var  = g_colsq[j] * (1.0f / N_NODES) - mean * mean;
    float sc = rsqrtf(var + 1e-5f) * gamma[j];
    s_scale[j] = sc;
    s_shift[j] = beta[j] - mean * sc;
    __syncthreads();
    int head = j >> 6, c = j & 63;
    float be = 0.f;
    if (c < 40) {
        int jo = head * 40 + c;
        for (int k = 0; k < 128; k++) {
            float w = W2[k * 80 + jo];
            g_W2p[k * 128 + j] = s_scale[k] * w;
            be += s_shift[k] * w;
        }
        g_attS2p[j] = as2[jo];
        g_attD2p[j] = ad2[jo];
    } else {
        for (int k = 0; k < 128; k++) g_W2p[k * 128 + j] = 0.f;
        g_attS2p[j] = 0.f;
        g_attD2p[j] = 0.f;
    }
    g_biasEff[j] = be;
}

// ---------------- launch ----------------
extern "C" void kernel_launch(void* const* d_in, const int* in_sizes, int n_in,
                              void* d_out, int out_size) {
    const float* x     = (const float*)d_in[0];
    const int*   ei    = (const int*)d_in[1];
    const float* W1    = (const float*)d_in[2];
    const float* as1   = (const float*)d_in[3];
    const float* ad1   = (const float*)d_in[4];
    const float* b1    = (const float*)d_in[5];
    const float* gamma = (const float*)d_in[6];
    const float* beta  = (const float*)d_in[7];
    const float* W2    = (const float*)d_in[8];
    const float* as2   = (const float*)d_in[9];
    const float* ad2   = (const float*)d_in[10];
    const float* b2    = (const float*)d_in[11];
    float* out = (float*)d_out;

    const int GEMM_BLOCKS = (N_NODES + 63) / 64;   // 1563
    const int WARP_BLOCKS = (N_NODES * 32) / 256;  // 12500

    bool forked = (g_s2 != nullptr);
    if (forked) {
        // fork: CSR build on g_s2, concurrent with GEMM1 on stream 0
        cudaEventRecord(g_e1, 0);
        cudaStreamWaitEvent(g_s2, g_e1, 0);
        init_k<<<(N_NODES + 255) / 256, 256, 0, g_s2>>>();
        count_k<<<(N_EDGES + 255) / 256, 256, 0, g_s2>>>(ei);
        scan1_k<<<SCAN_NB, 1024, 0, g_s2>>>();
        scan2_k<<<1, 128, 0, g_s2>>>();
        scan3_k<<<SCAN_NB, 1024, 0, g_s2>>>();
        fill_k<<<(TOT_E + 255) / 256, 256, 0, g_s2>>>(ei);
        cudaEventRecord(g_e2, g_s2);
    } else {
        init_k<<<(N_NODES + 255) / 256, 256>>>();
        count_k<<<(N_EDGES + 255) / 256, 256>>>(ei);
        scan1_k<<<SCAN_NB, 1024>>>();
        scan2_k<<<1, 128>>>();
        scan3_k<<<SCAN_NB, 1024>>>();
        fill_k<<<(TOT_E + 255) / 256, 256>>>(ei);
    }

    // layer 1 projection + attention dots (independent of CSR)
    gemm_att_k<1><<<GEMM_BLOCKS, 256>>>(x, W1, b1, as1, ad1);

    if (forked) cudaStreamWaitEvent(0, g_e2, 0);   // join CSR before aggregation

    agg_k<1><<<WARP_BLOCKS, 256>>>(b1, nullptr);

    // batch-norm fold
    bn_stats_k<<<256, dim3(32, 8)>>>();
    prep_k<<<1, 128>>>(gamma, beta, W2, as2, ad2);

    // layer 2 (BN folded) + fused mean/bias/log_softmax
    gemm_att_k<2><<<GEMM_BLOCKS, 256>>>(nullptr, nullptr, nullptr, nullptr, nullptr);
    agg_k<2><<<WARP_BLOCKS, 256>>>(b2, out);
}